// round 1
// baseline (speedup 1.0000x reference)
#include <cuda_runtime.h>

// Problem constants (VQDecoderO2M): B=4096, HIDDEN=128, D_IO=80, SEQ=512
#define NB      4096
#define H       128
#define G4      512        // 4*H gate rows
#define DIO     80
#define TSTEPS  512

#define ROWS    16         // batch rows per CTA
#define NBLK    (NB / ROWS)  // 256 CTAs
#define NTHR    256

// ---------------- device-global scratch (allowed; no runtime allocation) ----
__device__ float d_WeffT[H * G4];  // [k][g]  (W_hh + W_ih@W_fc)^T
__device__ float d_WhhT [H * G4];  // [k][g]  W_hh^T   (step 0 only)
__device__ float d_WfcT [H * DIO]; // [u][d]  W_fc^T
__device__ float d_beff [G4];      // b_ih + b_hh + W_ih@b_fc
__device__ float d_b0   [G4];      // b_ih + b_hh

// ---------------- prep: fold the input path into the recurrence -------------
// W_eff = W_hh + W_ih @ W_fc ; stored transposed [k][g] for coalesced reads.
__global__ void prep_w(const float* __restrict__ W_ih, const float* __restrict__ W_hh,
                       const float* __restrict__ b_ih, const float* __restrict__ b_hh,
                       const float* __restrict__ W_fc, const float* __restrict__ b_fc) {
    int g = blockIdx.x;      // 0..511
    int k = threadIdx.x;     // 0..127
    float whh = W_hh[g * H + k];
    float acc = 0.0f;
    #pragma unroll 4
    for (int d = 0; d < DIO; ++d)
        acc = fmaf(W_ih[g * DIO + d], W_fc[d * H + k], acc);
    d_WhhT [k * G4 + g] = whh;
    d_WeffT[k * G4 + g] = whh + acc;
    if (k == 0) {
        float bb = b_ih[g] + b_hh[g];
        float bd = 0.0f;
        for (int d = 0; d < DIO; ++d)
            bd = fmaf(W_ih[g * DIO + d], b_fc[d], bd);
        d_b0[g]   = bb;
        d_beff[g] = bb + bd;
    }
}

__global__ void prep_fc(const float* __restrict__ W_fc) {
    int u = blockIdx.x;      // 0..127
    int d = threadIdx.x;     // 0..79
    d_WfcT[u * DIO + d] = W_fc[d * H + u];
}

// ---------------- main persistent recurrence kernel -------------------------
__device__ __forceinline__ float sigf(float x) {
    // sigmoid via EX2 + RCP (accurate fast path; ~1e-7 abs err)
    return __fdividef(1.0f, 1.0f + __expf(-x));
}

extern __shared__ float smem[];

__global__ __launch_bounds__(NTHR, 2)
void lstm_main(const float* __restrict__ h0, float* __restrict__ out,
               const float* __restrict__ b_fc) {
    float* h_sm   = smem;                       // ROWS*H   = 2048 f
    float* c_sm   = h_sm + ROWS * H;            // ROWS*H   = 2048 f
    float* g_sm   = c_sm + ROWS * H;            // ROWS*G4  = 8192 f
    float* wfc_sm = g_sm + ROWS * G4;           // H*DIO    = 10240 f

    const int t = threadIdx.x;
    const int row_base = blockIdx.x * ROWS;

    // init: h = quantized_hn rows, c = 0, stage W_fc^T in smem (reused 512x)
    for (int i = t; i < ROWS * H; i += NTHR) {
        int r = i >> 7, u = i & 127;
        h_sm[i] = h0[(size_t)(row_base + r) * H + u];
        c_sm[i] = 0.0f;
    }
    for (int i = t; i < H * DIO; i += NTHR)
        wfc_sm[i] = d_WfcT[i];
    __syncthreads();

    // Phase-A thread tile: 8 rows x 4 gate-cols
    const int r0 = (t >> 7) * 8;        // 0 or 8
    const int g0 = (t & 127) * 4;       // 0..508

    for (int step = 0; step < TSTEPS; ++step) {
        const float* __restrict__ Wt = (step == 0) ? d_WhhT : d_WeffT;
        const float* __restrict__ bt = (step == 0) ? d_b0   : d_beff;

        // ---------- Phase A: gates[16][512] = h[16][128] @ W_T ----------
        float4 acc[8];
        #pragma unroll
        for (int i = 0; i < 8; ++i) acc[i] = make_float4(0.f, 0.f, 0.f, 0.f);

        #pragma unroll 2
        for (int k0 = 0; k0 < H; k0 += 4) {
            float4 w0 = *(const float4*)&Wt[(k0 + 0) * G4 + g0];
            float4 w1 = *(const float4*)&Wt[(k0 + 1) * G4 + g0];
            float4 w2 = *(const float4*)&Wt[(k0 + 2) * G4 + g0];
            float4 w3 = *(const float4*)&Wt[(k0 + 3) * G4 + g0];
            #pragma unroll
            for (int i = 0; i < 8; ++i) {
                float4 hv = *(const float4*)&h_sm[(r0 + i) * H + k0];
                acc[i].x = fmaf(hv.x, w0.x, acc[i].x);
                acc[i].x = fmaf(hv.y, w1.x, acc[i].x);
                acc[i].x = fmaf(hv.z, w2.x, acc[i].x);
                acc[i].x = fmaf(hv.w, w3.x, acc[i].x);
                acc[i].y = fmaf(hv.x, w0.y, acc[i].y);
                acc[i].y = fmaf(hv.y, w1.y, acc[i].y);
                acc[i].y = fmaf(hv.z, w2.y, acc[i].y);
                acc[i].y = fmaf(hv.w, w3.y, acc[i].y);
                acc[i].z = fmaf(hv.x, w0.z, acc[i].z);
                acc[i].z = fmaf(hv.y, w1.z, acc[i].z);
                acc[i].z = fmaf(hv.z, w2.z, acc[i].z);
                acc[i].z = fmaf(hv.w, w3.z, acc[i].z);
                acc[i].w = fmaf(hv.x, w0.w, acc[i].w);
                acc[i].w = fmaf(hv.y, w1.w, acc[i].w);
                acc[i].w = fmaf(hv.z, w2.w, acc[i].w);
                acc[i].w = fmaf(hv.w, w3.w, acc[i].w);
            }
        }
        {
            float4 bv = *(const float4*)&bt[g0];
            #pragma unroll
            for (int i = 0; i < 8; ++i) {
                float4 v;
                v.x = acc[i].x + bv.x;
                v.y = acc[i].y + bv.y;
                v.z = acc[i].z + bv.z;
                v.w = acc[i].w + bv.w;
                *(float4*)&g_sm[(r0 + i) * G4 + g0] = v;
            }
        }
        __syncthreads();

        // ---------- Phase B: LSTM elementwise (i,f,g,o), update h,c ------
        #pragma unroll
        for (int j = 0; j < (ROWS * H) / NTHR; ++j) {   // 8 elems/thread
            int idx = t + j * NTHR;
            int r = idx >> 7, u = idx & 127;
            const float* gr = &g_sm[r * G4];
            float gi = gr[u];
            float gf = gr[128 + u];
            float gg = gr[256 + u];
            float go = gr[384 + u];
            float cc = c_sm[idx];
            float si = sigf(gi);
            float sf = sigf(gf);
            float so = sigf(go);
            float tg = fmaf(2.0f, sigf(2.0f * gg), -1.0f);     // tanh(g)
            float cn = fmaf(sf, cc, si * tg);
            float tc = fmaf(2.0f, sigf(2.0f * cn), -1.0f);     // tanh(c')
            float hn = so * tc;
            c_sm[idx] = cn;
            h_sm[idx] = hn;
        }
        __syncthreads();

        // ---------- Phase C: y[16][80] = h_new @ W_fc^T + b_fc, store ----
        // 160 tasks of (2 rows x 4 d-cols)
        if (t < 160) {
            int rp = t / 20;
            int d0 = (t % 20) * 4;
            int ra = rp * 2, rb = ra + 1;
            float4 bfc = *(const float4*)&b_fc[d0];
            float4 ya = bfc, yb = bfc;
            #pragma unroll 4
            for (int u = 0; u < H; ++u) {
                float4 wv = *(const float4*)&wfc_sm[u * DIO + d0];
                float ha = h_sm[ra * H + u];
                float hb = h_sm[rb * H + u];
                ya.x = fmaf(ha, wv.x, ya.x);
                ya.y = fmaf(ha, wv.y, ya.y);
                ya.z = fmaf(ha, wv.z, ya.z);
                ya.w = fmaf(ha, wv.w, ya.w);
                yb.x = fmaf(hb, wv.x, yb.x);
                yb.y = fmaf(hb, wv.y, yb.y);
                yb.z = fmaf(hb, wv.z, yb.z);
                yb.w = fmaf(hb, wv.w, yb.w);
            }
            size_t oa = ((size_t)(row_base + ra) * TSTEPS + step) * DIO + d0;
            size_t ob = ((size_t)(row_base + rb) * TSTEPS + step) * DIO + d0;
            *(float4*)&out[oa] = ya;
            *(float4*)&out[ob] = yb;
        }
        // no extra sync needed: next Phase A only READS h_sm (as does C);
        // the post-A __syncthreads separates C's reads from next B's writes.
    }
}

// ---------------- launch ----------------------------------------------------
extern "C" void kernel_launch(void* const* d_in, const int* in_sizes, int n_in,
                              void* d_out, int out_size) {
    const float* h0   = (const float*)d_in[0];  // quantized_hn (4096,128)
    const float* W_ih = (const float*)d_in[1];  // (512,80)
    const float* W_hh = (const float*)d_in[2];  // (512,128)
    const float* b_ih = (const float*)d_in[3];  // (512)
    const float* b_hh = (const float*)d_in[4];  // (512)
    const float* W_fc = (const float*)d_in[5];  // (80,128)
    const float* b_fc = (const float*)d_in[6];  // (80)
    // d_in[7] = seq_len (fixed 512, compiled in)

    prep_w<<<G4, H>>>(W_ih, W_hh, b_ih, b_hh, W_fc, b_fc);
    prep_fc<<<H, DIO>>>(W_fc);

    int smem_bytes = (ROWS * H + ROWS * H + ROWS * G4 + H * DIO) * (int)sizeof(float); // 90112
    cudaFuncSetAttribute(lstm_main, cudaFuncAttributeMaxDynamicSharedMemorySize, smem_bytes);
    lstm_main<<<NBLK, NTHR, smem_bytes>>>(h0, (float*)d_out, b_fc);
}